// round 5
// baseline (speedup 1.0000x reference)
#include <cuda_runtime.h>
#include <cuda_fp16.h>
#include <cstdint>

#define KDIM 4096
#define ODIM 11008
#define KW   1376            // ODIM/8
#define BM 128
#define BN 256
#define BKK 64
#define NSTG 64              // KDIM/BKK

#define ASZ 16384            // 128 rows x 128B
#define BSZ 32768            // 256 rows x 128B
#define STG (ASZ + BSZ)      // 49152
#define SMEM_TOTAL (3 * STG) // 147456, 3 stages

__device__ __half g_x16[(size_t)4096 * 4096];     // x as fp16, [M][K]
__device__ __half g_w16[(size_t)11008 * 4096];    // dequant weights fp16, [O][K]

// ---------------- pre-kernel 1: x fp32 -> fp16 ----------------
__global__ __launch_bounds__(256)
void cvt_x(const float* __restrict__ x) {
    size_t i = ((size_t)blockIdx.x * 256 + threadIdx.x) * 4;
    float4 v = *(const float4*)(x + i);
    __half2 h0 = __floats2half2_rn(v.x, v.y);
    __half2 h1 = __floats2half2_rn(v.z, v.w);
    uint2 u;
    u.x = *(unsigned*)&h0;
    u.y = *(unsigned*)&h1;
    *(uint2*)(g_x16 + i) = u;
}

// ------- pre-kernel 2: dequantize weights to fp16 [O][K] -------
__global__ __launch_bounds__(256)
void dequant_w(const int* __restrict__ qweight, const float* __restrict__ scales,
               const int* __restrict__ qzeros) {
    const int w  = blockIdx.x * 32 + (threadIdx.x & 31);   // packed word col 0..1375
    const int kb = blockIdx.y * 8  + (threadIdx.x >> 5);   // 16-k block 0..255
    const int g  = kb >> 3;                                // quant group

    int qw[16];
    #pragma unroll
    for (int i = 0; i < 16; i++)
        qw[i] = qweight[(size_t)(kb * 16 + i) * KW + w];   // coalesced over lanes
    const int zw = qzeros[(size_t)g * KW + w];
    const float4 s0 = *(const float4*)(scales + (size_t)g * ODIM + w * 8);
    const float4 s1 = *(const float4*)(scales + (size_t)g * ODIM + w * 8 + 4);
    const float sv[8] = {s0.x, s0.y, s0.z, s0.w, s1.x, s1.y, s1.z, s1.w};

    #pragma unroll
    for (int j = 0; j < 8; j++) {                          // output col n = w*8 + j
        const int z = (zw >> (4 * j)) & 15;
        const float s = sv[j];
        unsigned u[8];
        #pragma unroll
        for (int p = 0; p < 8; p++) {
            float f0 = (float)(((qw[2 * p]     >> (4 * j)) & 15) - z) * s;
            float f1 = (float)(((qw[2 * p + 1] >> (4 * j)) & 15) - z) * s;
            __half2 h = __floats2half2_rn(f0, f1);         // low half = k even
            u[p] = *(unsigned*)&h;
        }
        __half* dst = g_w16 + (size_t)(w * 8 + j) * KDIM + kb * 16;
        *(uint4*)dst       = make_uint4(u[0], u[1], u[2], u[3]);
        *(uint4*)(dst + 8) = make_uint4(u[4], u[5], u[6], u[7]);
    }
}

// ---------------- helpers ----------------
#define CP16(dst, src) \
    asm volatile("cp.async.cg.shared.global [%0], [%1], 16;" :: "r"(dst), "l"(src))

static __device__ __forceinline__ void ldsm_x4(unsigned* r, unsigned addr) {
    asm volatile("ldmatrix.sync.aligned.m8n8.x4.shared.b16 {%0,%1,%2,%3}, [%4];"
                 : "=r"(r[0]), "=r"(r[1]), "=r"(r[2]), "=r"(r[3]) : "r"(addr));
}
static __device__ __forceinline__ void mma_f16(float* c, const unsigned* a,
                                               const unsigned* b) {
    asm volatile(
        "mma.sync.aligned.m16n8k16.row.col.f32.f16.f16.f32 "
        "{%0,%1,%2,%3}, {%4,%5,%6,%7}, {%8,%9}, {%0,%1,%2,%3};"
        : "+f"(c[0]), "+f"(c[1]), "+f"(c[2]), "+f"(c[3])
        : "r"(a[0]), "r"(a[1]), "r"(a[2]), "r"(a[3]), "r"(b[0]), "r"(b[1]));
}

// ---------------- main fp16 GEMM: CTA 128x256, warp 64x64 ----------------
__global__ __launch_bounds__(256)
void w4_hgemm(float* __restrict__ out) {
    extern __shared__ char smem[];
    const int tid  = threadIdx.x;
    const int lane = tid & 31;
    const int wid  = tid >> 5;
    const int wm   = wid >> 2;                 // 0..1  (64 rows)
    const int wn   = wid & 3;                  // 0..3  (64 cols)
    const int bm0  = blockIdx.x * BM;          // bm FAST -> B slab reuse across wave
    const int bn0  = blockIdx.y * BN;

    const char* ga = (const char*)(g_x16 + (size_t)bm0 * KDIM);   // bytes
    const char* gb = (const char*)(g_w16 + (size_t)bn0 * KDIM);

    float acc[4][8][4];
    #pragma unroll
    for (int i = 0; i < 4; i++)
        #pragma unroll
        for (int j = 0; j < 8; j++)
            #pragma unroll
            for (int q = 0; q < 4; q++) acc[i][j][q] = 0.0f;

    auto issue = [&](int t) {
        char* s = smem + (t % 3) * STG;
        #pragma unroll
        for (int i = 0; i < 4; i++) {            // A: 1024 chunks
            const int idx = tid + 256 * i;
            const int row = idx >> 3;            // 0..127
            const int ch  = idx & 7;
            unsigned d = (unsigned)__cvta_generic_to_shared(
                s + row * 128 + ((ch ^ (row & 7)) * 16));
            CP16(d, ga + (size_t)row * 8192 + (size_t)t * 128 + ch * 16);
        }
        #pragma unroll
        for (int i = 0; i < 8; i++) {            // B: 2048 chunks
            const int idx = tid + 256 * i;
            const int n  = idx >> 3;             // 0..255
            const int ch = idx & 7;
            unsigned d = (unsigned)__cvta_generic_to_shared(
                s + ASZ + n * 128 + ((ch ^ (n & 7)) * 16));
            CP16(d, gb + (size_t)n * 8192 + (size_t)t * 128 + ch * 16);
        }
        asm volatile("cp.async.commit_group;");
    };

    issue(0);
    issue(1);
    issue(2);

    const int arow = lane & 15;
    const int asel = lane >> 4;
    const int bg   = lane >> 3;                  // 0..3 matrix group
    const int r = lane >> 2;                     // 0..7
    const int c = lane & 3;                      // 0..3

    #pragma unroll 1
    for (int t = 0; t < NSTG; t++) {
        if (t < NSTG - 2)      asm volatile("cp.async.wait_group 2;");
        else if (t == NSTG - 2) asm volatile("cp.async.wait_group 1;");
        else                   asm volatile("cp.async.wait_group 0;");
        __syncthreads();

        const char* As = smem + (t % 3) * STG;
        const char* Bs = As + ASZ;

        #pragma unroll
        for (int ks = 0; ks < 4; ks++) {         // 4 x k16 steps = BKK 64
            unsigned a[4][4], b[8][2];
            #pragma unroll
            for (int mt = 0; mt < 4; mt++) {
                const int row = wm * 64 + mt * 16 + arow;
                const int ch  = 2 * ks + asel;
                unsigned ad = (unsigned)__cvta_generic_to_shared(
                    As + row * 128 + ((ch ^ (row & 7)) * 16));
                ldsm_x4(a[mt], ad);
            }
            #pragma unroll
            for (int p = 0; p < 4; p++) {        // each x4 fills frags 2p, 2p+1
                const int n  = wn * 64 + p * 16 + ((bg >> 1) << 3) + (lane & 7);
                const int ch = 2 * ks + (bg & 1);
                unsigned bd = (unsigned)__cvta_generic_to_shared(
                    Bs + n * 128 + ((ch ^ (n & 7)) * 16));
                ldsm_x4(&b[2 * p][0], bd);
            }
            #pragma unroll
            for (int mt = 0; mt < 4; mt++)
                #pragma unroll
                for (int nt = 0; nt < 8; nt++)
                    mma_f16(acc[mt][nt], a[mt], b[nt]);
        }
        __syncthreads();
        if (t + 3 < NSTG) issue(t + 3);
    }

    // ---- epilogue: streaming stores (keep A/B resident in L2) ----
    #pragma unroll
    for (int mt = 0; mt < 4; mt++) {
        #pragma unroll
        for (int nt = 0; nt < 8; nt++) {
            const int row = bm0 + wm * 64 + mt * 16 + r;
            const int col = bn0 + wn * 64 + nt * 8 + c * 2;
            float* p = out + (size_t)row * ODIM + col;
            __stcs((float2*)p, make_float2(acc[mt][nt][0], acc[mt][nt][1]));
            __stcs((float2*)(p + (size_t)8 * ODIM),
                   make_float2(acc[mt][nt][2], acc[mt][nt][3]));
        }
    }
}

extern "C" void kernel_launch(void* const* d_in, const int* in_sizes, int n_in,
                              void* d_out, int out_size) {
    const float* x       = (const float*)d_in[0];
    const int*   qweight = (const int*)d_in[1];
    const float* scales  = (const float*)d_in[2];
    const int*   qzeros  = (const int*)d_in[3];
    float*       out     = (float*)d_out;

    const int M = in_sizes[0] / KDIM;            // 4096

    cvt_x<<<(M * KDIM) / (256 * 4), 256>>>(x);
    dequant_w<<<dim3(KW / 32, 32), 256>>>(qweight, scales, qzeros);  // (43,32)

    cudaFuncSetAttribute(w4_hgemm, cudaFuncAttributeMaxDynamicSharedMemorySize, SMEM_TOTAL);
    dim3 grid(M / BM, ODIM / BN);                // (32, 43) — bm fast
    w4_hgemm<<<grid, 256, SMEM_TOTAL>>>(out);
}

// round 6
// speedup vs baseline: 1.1365x; 1.1365x over previous
#include <cuda_runtime.h>
#include <cuda_fp16.h>
#include <cstdint>

#define KDIM 4096
#define ODIM 11008
#define KW   1376            // ODIM/8
#define BM 128
#define BN 128
#define BKK 64
#define NSTG 64              // KDIM/BKK

#define ASZ 16384            // 128 rows x 128B (64 f16)
#define STG 32768            // A + B per stage
#define SMEM_TOTAL 98304     // 3 stages

__device__ __half g_x16[(size_t)4096 * 4096];     // x as fp16, [M][K]
__device__ __half g_w16[(size_t)11008 * 4096];    // dequant weights fp16, [O][K]

// ---------------- pre-kernel 1: x fp32 -> fp16 ----------------
__global__ __launch_bounds__(256)
void cvt_x(const float* __restrict__ x) {
    size_t i = ((size_t)blockIdx.x * 256 + threadIdx.x) * 4;
    float4 v = *(const float4*)(x + i);
    __half2 h0 = __floats2half2_rn(v.x, v.y);
    __half2 h1 = __floats2half2_rn(v.z, v.w);
    uint2 u;
    u.x = *(unsigned*)&h0;
    u.y = *(unsigned*)&h1;
    *(uint2*)(g_x16 + i) = u;
}

// ------- pre-kernel 2: dequantize weights to fp16 [O][K] -------
__global__ __launch_bounds__(256)
void dequant_w(const int* __restrict__ qweight, const float* __restrict__ scales,
               const int* __restrict__ qzeros) {
    const int w  = blockIdx.x * 32 + (threadIdx.x & 31);   // packed word col 0..1375
    const int kb = blockIdx.y * 8  + (threadIdx.x >> 5);   // 16-k block 0..255
    const int g  = kb >> 3;                                // quant group

    int qw[16];
    #pragma unroll
    for (int i = 0; i < 16; i++)
        qw[i] = qweight[(size_t)(kb * 16 + i) * KW + w];   // coalesced over lanes
    const int zw = qzeros[(size_t)g * KW + w];
    const float4 s0 = *(const float4*)(scales + (size_t)g * ODIM + w * 8);
    const float4 s1 = *(const float4*)(scales + (size_t)g * ODIM + w * 8 + 4);
    const float sv[8] = {s0.x, s0.y, s0.z, s0.w, s1.x, s1.y, s1.z, s1.w};

    #pragma unroll
    for (int j = 0; j < 8; j++) {                          // output col n = w*8 + j
        const int z = (zw >> (4 * j)) & 15;
        const float s = sv[j];
        unsigned u[8];
        #pragma unroll
        for (int p = 0; p < 8; p++) {
            float f0 = (float)(((qw[2 * p]     >> (4 * j)) & 15) - z) * s;
            float f1 = (float)(((qw[2 * p + 1] >> (4 * j)) & 15) - z) * s;
            __half2 h = __floats2half2_rn(f0, f1);         // low half = k even
            u[p] = *(unsigned*)&h;
        }
        __half* dst = g_w16 + (size_t)(w * 8 + j) * KDIM + kb * 16;
        *(uint4*)dst       = make_uint4(u[0], u[1], u[2], u[3]);
        *(uint4*)(dst + 8) = make_uint4(u[4], u[5], u[6], u[7]);
    }
}

// ---------------- helpers ----------------
#define CP16(dst, src) \
    asm volatile("cp.async.cg.shared.global [%0], [%1], 16;" :: "r"(dst), "l"(src))

static __device__ __forceinline__ void ldsm_x4(unsigned* r, unsigned addr) {
    asm volatile("ldmatrix.sync.aligned.m8n8.x4.shared.b16 {%0,%1,%2,%3}, [%4];"
                 : "=r"(r[0]), "=r"(r[1]), "=r"(r[2]), "=r"(r[3]) : "r"(addr));
}
static __device__ __forceinline__ void mma_f16(float* c, const unsigned* a,
                                               const unsigned* b) {
    asm volatile(
        "mma.sync.aligned.m16n8k16.row.col.f32.f16.f16.f32 "
        "{%0,%1,%2,%3}, {%4,%5,%6,%7}, {%8,%9}, {%0,%1,%2,%3};"
        : "+f"(c[0]), "+f"(c[1]), "+f"(c[2]), "+f"(c[3])
        : "r"(a[0]), "r"(a[1]), "r"(a[2]), "r"(a[3]), "r"(b[0]), "r"(b[1]));
}

// ---------------- main fp16 GEMM: CTA 128x128, warp 64x32, 2 CTAs/SM ----------------
__global__ __launch_bounds__(256, 2)
void w4_hgemm(float* __restrict__ out) {
    extern __shared__ char smem[];
    const int tid  = threadIdx.x;
    const int lane = tid & 31;
    const int wid  = tid >> 5;
    const int wm   = wid >> 2;                 // 0..1  (64 rows)
    const int wn   = wid & 3;                  // 0..3  (32 cols)
    const int bm0  = blockIdx.x * BM;          // bm FAST -> B slab reused across wave
    const int bn0  = blockIdx.y * BN;

    const char* ga = (const char*)(g_x16 + (size_t)bm0 * KDIM);   // bytes
    const char* gb = (const char*)(g_w16 + (size_t)bn0 * KDIM);

    float acc[4][4][4];
    #pragma unroll
    for (int i = 0; i < 4; i++)
        #pragma unroll
        for (int j = 0; j < 4; j++)
            #pragma unroll
            for (int q = 0; q < 4; q++) acc[i][j][q] = 0.0f;

    auto issue = [&](int t) {
        char* s = smem + (t % 3) * STG;
        #pragma unroll
        for (int i = 0; i < 4; i++) {            // A: 1024 16B chunks
            const int idx = tid + 256 * i;
            const int row = idx >> 3;            // 0..127
            const int ch  = idx & 7;
            const int so  = row * 128 + ((ch ^ (row & 7)) * 16);
            const size_t go = (size_t)row * 8192 + (size_t)t * 128 + ch * 16;
            unsigned da = (unsigned)__cvta_generic_to_shared(s + so);
            CP16(da, ga + go);
            unsigned db = (unsigned)__cvta_generic_to_shared(s + ASZ + so);
            CP16(db, gb + go);
        }
        asm volatile("cp.async.commit_group;");
    };

    issue(0);
    issue(1);

    const int arow = lane & 15;                 // ldmatrix x4 A row-provider
    const int asel = lane >> 4;                 // 0: k-lo chunk, 1: k-hi
    const int bg   = lane >> 3;                 // 0..3 B matrix group
    const int r = lane >> 2;                    // 0..7
    const int c = lane & 3;                     // 0..3

    #pragma unroll 1
    for (int t = 0; t < NSTG; t++) {
        if (t + 1 < NSTG) asm volatile("cp.async.wait_group 1;");
        else              asm volatile("cp.async.wait_group 0;");
        __syncthreads();
        if (t + 2 < NSTG) issue(t + 2);          // buffer (t+2)%3: readers done at t-1

        const char* As = smem + (t % 3) * STG;
        const char* Bs = As + ASZ;

        #pragma unroll
        for (int ks = 0; ks < 4; ks++) {        // 4 x k16 steps = BKK 64
            unsigned a[4][4], b[4][2];
            #pragma unroll
            for (int mt = 0; mt < 4; mt++) {
                const int row = wm * 64 + mt * 16 + arow;
                const int ch  = 2 * ks + asel;
                unsigned ad = (unsigned)__cvta_generic_to_shared(
                    As + row * 128 + ((ch ^ (row & 7)) * 16));
                ldsm_x4(a[mt], ad);
            }
            #pragma unroll
            for (int p = 0; p < 2; p++) {        // each x4 fills frags 2p, 2p+1
                const int n  = wn * 32 + p * 16 + ((bg >> 1) << 3) + (lane & 7);
                const int ch = 2 * ks + (bg & 1);
                unsigned bd = (unsigned)__cvta_generic_to_shared(
                    Bs + n * 128 + ((ch ^ (n & 7)) * 16));
                ldsm_x4(&b[2 * p][0], bd);
            }
            #pragma unroll
            for (int mt = 0; mt < 4; mt++)
                #pragma unroll
                for (int nt = 0; nt < 4; nt++)
                    mma_f16(acc[mt][nt], a[mt], b[nt]);
        }
    }

    // ---- epilogue: streaming stores (keep A/B resident in L2) ----
    #pragma unroll
    for (int mt = 0; mt < 4; mt++) {
        #pragma unroll
        for (int nt = 0; nt < 4; nt++) {
            const int row = bm0 + wm * 64 + mt * 16 + r;
            const int col = bn0 + wn * 32 + nt * 8 + c * 2;
            float* p = out + (size_t)row * ODIM + col;
            __stcs((float2*)p, make_float2(acc[mt][nt][0], acc[mt][nt][1]));
            __stcs((float2*)(p + (size_t)8 * ODIM),
                   make_float2(acc[mt][nt][2], acc[mt][nt][3]));
        }
    }
}

extern "C" void kernel_launch(void* const* d_in, const int* in_sizes, int n_in,
                              void* d_out, int out_size) {
    const float* x       = (const float*)d_in[0];
    const int*   qweight = (const int*)d_in[1];
    const float* scales  = (const float*)d_in[2];
    const int*   qzeros  = (const int*)d_in[3];
    float*       out     = (float*)d_out;

    const int M = in_sizes[0] / KDIM;            // 4096

    cvt_x<<<(M * KDIM) / (256 * 4), 256>>>(x);
    dequant_w<<<dim3(KW / 32, 32), 256>>>(qweight, scales, qzeros);  // (43,32)

    cudaFuncSetAttribute(w4_hgemm, cudaFuncAttributeMaxDynamicSharedMemorySize, SMEM_TOTAL);
    dim3 grid(M / BM, ODIM / BN);                // (32, 86) — bm fast
    w4_hgemm<<<grid, 256, SMEM_TOTAL>>>(out);
}